// round 14
// baseline (speedup 1.0000x reference)
#include <cuda_runtime.h>
#include <cuda_fp16.h>
#include <math.h>
#include <stdint.h>

#define E_EDGES   4096
#define COMB_DIM  256
#define REL_DIM   128
#define IN_DIM    512
#define HID_DIM   1024
#define NE        50000
#define KDIM      1024           // GEMM2 K (plain fp16)
#define K1P       1536           // GEMM1 K' = 3 * 512 (hi/lo/hi split)
#define NPAD      50176          // 392 * 128
#define BM        128
#define BN        128
#define BK        64

// ---------------- device scratch (allocation-free rule) ----------------
__device__ float  g_row_lp[E_EDGES];
__device__ __half g_embh[(size_t)E_EDGES * K1P];     // 12 MB  (A of gemm1, triple)
__device__ __half g_W1T[(size_t)HID_DIM * K1P];      // 3 MB   (B of gemm1, triple)
__device__ __half g_A2[(size_t)E_EDGES * KDIM];      // 8 MB   (fp16 h)
__device__ __half g_B2[(size_t)NPAD * KDIM];         // 103 MB (fp16 W2^T)

// ---------------- PTX helpers ----------------
__device__ __forceinline__ uint32_t smem_u32(const void* p) {
    uint32_t a;
    asm("{ .reg .u64 t; cvta.to.shared.u64 t, %1; cvt.u32.u64 %0, t; }"
        : "=r"(a) : "l"(p));
    return a;
}
#define CP_ASYNC16(smem, gptr) \
    asm volatile("cp.async.cg.shared.global [%0], [%1], 16;" \
                 :: "r"(smem), "l"(gptr) : "memory")
#define CP_COMMIT() asm volatile("cp.async.commit_group;" ::: "memory")
#define CP_WAIT(n)  asm volatile("cp.async.wait_group %0;" :: "n"(n) : "memory")

#define LDMATRIX_X4(r0, r1, r2, r3, addr) \
    asm volatile("ldmatrix.sync.aligned.m8n8.x4.shared.b16 {%0,%1,%2,%3}, [%4];" \
                 : "=r"(r0), "=r"(r1), "=r"(r2), "=r"(r3) : "r"(addr))

#define MMA16816(d, a, b0, b1) \
    asm volatile("mma.sync.aligned.m16n8k16.row.col.f32.f16.f16.f32 " \
                 "{%0,%1,%2,%3}, {%4,%5,%6,%7}, {%8,%9}, {%0,%1,%2,%3};" \
                 : "+f"((d)[0]), "+f"((d)[1]), "+f"((d)[2]), "+f"((d)[3]) \
                 : "r"((a)[0]), "r"((a)[1]), "r"((a)[2]), "r"((a)[3]), \
                   "r"(b0), "r"(b1))

#define SWZ(off) ((off) ^ (((off) >> 3) & 0x70))

// ---------------------------------------------------------------------------
// 1) Gather -> fp16 triple [hi, lo, hi] per source value (row = 1536 halves)
// ---------------------------------------------------------------------------
__global__ void gather_kernel(const float* __restrict__ comb,
                              const float* __restrict__ rel,
                              const float* __restrict__ dyn,
                              const int* __restrict__ edge_index,
                              const int* __restrict__ edge_type) {
    int e = blockIdx.x;
    int head = edge_index[e];
    int rt   = edge_type[e];
    int col = threadIdx.x * 4;
    float4 v;
    if (col < COMB_DIM) {
        v = *(const float4*)(comb + (size_t)head * COMB_DIM + col);
    } else if (col < COMB_DIM + REL_DIM) {
        v = *(const float4*)(rel + (size_t)rt * REL_DIM + (col - COMB_DIM));
    } else {
        int d = col - (COMB_DIM + REL_DIM);
        const float* base = dyn + (size_t)rt * (4 * REL_DIM * 2) + 3 * (REL_DIM * 2);
        v.x = base[2 * (d + 0) + 1]; v.y = base[2 * (d + 1) + 1];
        v.z = base[2 * (d + 2) + 1]; v.w = base[2 * (d + 3) + 1];
    }
    __half2* dst = (__half2*)(g_embh + (size_t)e * K1P + 3 * (size_t)col);
    float x[4] = {v.x, v.y, v.z, v.w};
    __half h[12];
#pragma unroll
    for (int i = 0; i < 4; i++) {
        __half hi = __float2half(x[i]);
        __half lo = __float2half(x[i] - __half2float(hi));
        h[3 * i] = hi; h[3 * i + 1] = lo; h[3 * i + 2] = hi;
    }
#pragma unroll
    for (int i = 0; i < 6; i++)
        dst[i] = __halves2half2(h[2 * i], h[2 * i + 1]);
}

// ---------------------------------------------------------------------------
// 2) W1[k][n] -> W1T[n][3k] = [hi, hi, lo]   (512 x 1024 -> 1024 x 1536)
// ---------------------------------------------------------------------------
__global__ void convW1_kernel(const float* __restrict__ W1,
                              __half* __restrict__ W1T) {
    __shared__ float tile[32][33];
    int k0 = blockIdx.x * 32;
    int n0 = blockIdx.y * 32;
    int tx = threadIdx.x, ty = threadIdx.y;   // 32 x 8
#pragma unroll
    for (int i = 0; i < 4; i++) {
        int k = k0 + ty + 8 * i, n = n0 + tx;
        tile[ty + 8 * i][tx] = W1[(size_t)k * HID_DIM + n];
    }
    __syncthreads();
#pragma unroll
    for (int i = 0; i < 4; i++) {
        int n = n0 + ty + 8 * i, k = k0 + tx;
        float x = tile[tx][ty + 8 * i];
        __half hi = __float2half(x);
        __half lo = __float2half(x - __half2float(hi));
        size_t o = (size_t)n * K1P + 3 * (size_t)k;
        W1T[o] = hi; W1T[o + 1] = hi; W1T[o + 2] = lo;
    }
}

// ---------------------------------------------------------------------------
// 3) W2[k][n] -> B2[n][k] fp16 transpose; zero rows for n >= NE
// ---------------------------------------------------------------------------
__global__ void convB_kernel(const float* __restrict__ W2,
                             __half* __restrict__ B2) {
    __shared__ float tile[32][33];
    int k0 = blockIdx.x * 32;
    int n0 = blockIdx.y * 32;
    int tx = threadIdx.x, ty = threadIdx.y;   // 32 x 8
#pragma unroll
    for (int i = 0; i < 4; i++) {
        int k = k0 + ty + 8 * i, n = n0 + tx;
        tile[ty + 8 * i][tx] = (n < NE) ? W2[(size_t)k * NE + n] : 0.0f;
    }
    __syncthreads();
#pragma unroll
    for (int i = 0; i < 4; i++) {
        int n = n0 + ty + 8 * i, k = k0 + tx;
        B2[(size_t)n * KDIM + k] = __float2half(tile[tx][ty + 8 * i]);
    }
}

// ---------------------------------------------------------------------------
// 4) Templated HMMA GEMM: 128x128 tile, BK=64, 3-stage cp.async, 8 warps
//    TANH_OUT=true : out = fp16 tanh(acc+bias), ldc = KDIM, no N guard
//    TANH_OUT=false: out = fp32 acc+bias,       ldc = NE,   N guard
// ---------------------------------------------------------------------------
#define STAGE_BYTES 32768       // 16KB A + 16KB B
#define SMEM_NEED   (3 * STAGE_BYTES + 1024)

template<int LD_BYTES, int NT, bool TANH_OUT>
__global__ __launch_bounds__(256)
void gemm_mma(const __half* __restrict__ A, const __half* __restrict__ B,
              const float* __restrict__ bias, void* __restrict__ Cv) {
    extern __shared__ char smem_raw[];
    char* smem = (char*)(((uintptr_t)smem_raw + 1023) & ~(uintptr_t)1023);
    const uint32_t sbase = smem_u32(smem);
    const int tid = threadIdx.x;
    const int wid = tid >> 5, lane = tid & 31;
    const int warp_m = wid >> 1;       // 0..3
    const int warp_n = wid & 1;        // 0..1
    const int bm = blockIdx.x * BM;
    const int bn = blockIdx.y * BN;

    const char* gA = (const char*)A;
    const char* gB = (const char*)B;

    auto load_tile = [&](int s, int t) {
        const size_t kb = (size_t)t * (BK * 2);
        uint32_t aS = sbase + s * STAGE_BYTES;
        uint32_t bS = aS + 16384;
#pragma unroll
        for (int i = 0; i < 4; i++) {
            int idx = tid + i * 256;
            int row = idx >> 3, c16 = idx & 7;
            uint32_t off = (uint32_t)(row * 128 + c16 * 16);
            CP_ASYNC16(aS + SWZ(off), gA + (size_t)(bm + row) * LD_BYTES + kb + c16 * 16);
        }
#pragma unroll
        for (int i = 0; i < 4; i++) {
            int idx = tid + i * 256;
            int row = idx >> 3, c16 = idx & 7;
            uint32_t off = (uint32_t)(row * 128 + c16 * 16);
            CP_ASYNC16(bS + SWZ(off), gB + (size_t)(bn + row) * LD_BYTES + kb + c16 * 16);
        }
    };

    float acc[2][8][4];
#pragma unroll
    for (int mi = 0; mi < 2; mi++)
#pragma unroll
        for (int nj = 0; nj < 8; nj++)
#pragma unroll
            for (int r = 0; r < 4; r++) acc[mi][nj][r] = 0.0f;

    const int a_row_in16 = ((lane >> 3) & 1) * 8 + (lane & 7);
    const int a_khalf16  = (lane >> 4);
    const int b_row_in16 = ((lane >> 4) << 3) + (lane & 7);
    const int b_khalf16  = (lane >> 3) & 1;

    load_tile(0, 0); CP_COMMIT();
    load_tile(1, 1); CP_COMMIT();

    for (int t = 0; t < NT; t++) {
        if (t + 2 < NT) { load_tile((t + 2) % 3, t + 2); CP_COMMIT(); CP_WAIT(2); }
        else if (t + 1 < NT) { CP_WAIT(1); }
        else { CP_WAIT(0); }
        __syncthreads();

        uint32_t aS = sbase + (t % 3) * STAGE_BYTES;
        uint32_t bS = aS + 16384;
#pragma unroll
        for (int kk = 0; kk < 4; kk++) {
            uint32_t a[2][4];
#pragma unroll
            for (int mi = 0; mi < 2; mi++) {
                int row = warp_m * 32 + mi * 16 + a_row_in16;
                uint32_t off = (uint32_t)(kk * 32 + a_khalf16 * 16) ^ ((row & 7) << 4);
                LDMATRIX_X4(a[mi][0], a[mi][1], a[mi][2], a[mi][3],
                            aS + row * 128 + off);
            }
            uint32_t b[4][4];
#pragma unroll
            for (int nb = 0; nb < 4; nb++) {
                int row = warp_n * 64 + nb * 16 + b_row_in16;
                uint32_t off = (uint32_t)(kk * 32 + b_khalf16 * 16) ^ ((row & 7) << 4);
                LDMATRIX_X4(b[nb][0], b[nb][1], b[nb][2], b[nb][3],
                            bS + row * 128 + off);
            }
#pragma unroll
            for (int mi = 0; mi < 2; mi++)
#pragma unroll
                for (int nj = 0; nj < 8; nj++) {
                    int nb = nj >> 1, hi = (nj & 1) * 2;
                    MMA16816(acc[mi][nj], a[mi], b[nb][hi], b[nb][hi + 1]);
                }
        }
        __syncthreads();
    }

    const int r0 = lane >> 2;
    const int c0 = (lane & 3) * 2;
    if (TANH_OUT) {
        __half* Ch = (__half*)Cv;
#pragma unroll
        for (int nj = 0; nj < 8; nj++) {
            int col = bn + warp_n * 64 + nj * 8 + c0;
            float bv0 = bias[col], bv1 = bias[col + 1];
#pragma unroll
            for (int mi = 0; mi < 2; mi++) {
                int row = bm + warp_m * 32 + mi * 16 + r0;
                *(__half2*)(Ch + (size_t)row * KDIM + col) =
                    __floats2half2_rn(tanhf(acc[mi][nj][0] + bv0),
                                      tanhf(acc[mi][nj][1] + bv1));
                *(__half2*)(Ch + (size_t)(row + 8) * KDIM + col) =
                    __floats2half2_rn(tanhf(acc[mi][nj][2] + bv0),
                                      tanhf(acc[mi][nj][3] + bv1));
            }
        }
    } else {
        float* C = (float*)Cv;
#pragma unroll
        for (int nj = 0; nj < 8; nj++) {
            int col = bn + warp_n * 64 + nj * 8 + c0;
            if (col >= NE) continue;
            float bv0 = bias[col], bv1 = bias[col + 1];
#pragma unroll
            for (int mi = 0; mi < 2; mi++) {
                int row = bm + warp_m * 32 + mi * 16 + r0;
                float* p0 = C + (size_t)row * NE + col;
                p0[0] = acc[mi][nj][0] + bv0;
                p0[1] = acc[mi][nj][1] + bv1;
                float* p1 = C + (size_t)(row + 8) * NE + col;
                p1[0] = acc[mi][nj][2] + bv0;
                p1[1] = acc[mi][nj][3] + bv1;
            }
        }
    }
}

// ---------------------------------------------------------------------------
// 5) Single-pass online logsumexp + label log-prob
// ---------------------------------------------------------------------------
__global__ void lse_kernel(const float* __restrict__ pred,
                           const int* __restrict__ target_tails,
                           const int* __restrict__ node_id) {
    int row = blockIdx.x;
    const float* p = pred + (size_t)row * NE;
    __shared__ float sm[256], ss[256];
    int tid = threadIdx.x;

    float m = -3.402823e38f, s = 0.0f;
    for (int j = tid; j < NE; j += 256) {
        float v = p[j];
        if (v > m) { s = s * __expf(m - v) + 1.0f; m = v; }
        else       { s += __expf(v - m); }
    }
    sm[tid] = m; ss[tid] = s;
    __syncthreads();
    for (int st = 128; st > 0; st >>= 1) {
        if (tid < st) {
            float m1 = sm[tid], m2 = sm[tid + st];
            float M = fmaxf(m1, m2);
            ss[tid] = ss[tid] * __expf(m1 - M) + ss[tid + st] * __expf(m2 - M);
            sm[tid] = M;
        }
        __syncthreads();
    }
    if (tid == 0) {
        int label = node_id[target_tails[row]];
        g_row_lp[row] = p[label] - (sm[0] + logf(ss[0]));
    }
}

__global__ void final_kernel(float* __restrict__ out, int scalar_off) {
    __shared__ float red[256];
    int tid = threadIdx.x;
    float s = 0.0f;
    for (int j = tid; j < E_EDGES; j += 256) s += g_row_lp[j];
    red[tid] = s;
    __syncthreads();
    for (int t = 128; t > 0; t >>= 1) {
        if (tid < t) red[tid] += red[tid + t];
        __syncthreads();
    }
    if (tid == 0 && scalar_off >= 1) out[0] = red[0] / (float)E_EDGES;
}

// ---------------------------------------------------------------------------
extern "C" void kernel_launch(void* const* d_in, const int* in_sizes, int n_in,
                              void* d_out, int out_size) {
    const float* comb         = (const float*)d_in[0];
    const float* rel          = (const float*)d_in[1];
    const float* dyn          = (const float*)d_in[2];
    const float* W1           = (const float*)d_in[3];
    const float* b1           = (const float*)d_in[4];
    const float* W2           = (const float*)d_in[5];
    const float* b2           = (const float*)d_in[6];
    const int*   edge_index   = (const int*)d_in[7];
    const int*   edge_type    = (const int*)d_in[8];
    const int*   target_tails = (const int*)d_in[9];
    const int*   node_id      = (const int*)d_in[10];
    float* out = (float*)d_out;

    long long total = (long long)E_EDGES * (long long)NE;
    int off = (int)((long long)out_size - total);
    if (off < 0) off = 0;
    float* pred = out + off;

    void *p_embh_v, *p_W1T_v, *p_A2_v, *p_B2_v;
    cudaGetSymbolAddress(&p_embh_v, g_embh);
    cudaGetSymbolAddress(&p_W1T_v, g_W1T);
    cudaGetSymbolAddress(&p_A2_v, g_A2);
    cudaGetSymbolAddress(&p_B2_v, g_B2);
    __half* p_embh = (__half*)p_embh_v;
    __half* p_W1T  = (__half*)p_W1T_v;
    __half* p_A2   = (__half*)p_A2_v;
    __half* p_B2   = (__half*)p_B2_v;

    static bool attr_set = false;
    if (!attr_set) {
        cudaFuncSetAttribute((const void*)gemm_mma<K1P * 2, K1P / BK, true>,
                             cudaFuncAttributeMaxDynamicSharedMemorySize, SMEM_NEED);
        cudaFuncSetAttribute((const void*)gemm_mma<KDIM * 2, KDIM / BK, false>,
                             cudaFuncAttributeMaxDynamicSharedMemorySize, SMEM_NEED);
        attr_set = true;
    }

    // big independent conversion first
    dim3 cbG(KDIM / 32, NPAD / 32);
    convB_kernel<<<cbG, dim3(32, 8)>>>(W2, p_B2);

    gather_kernel<<<E_EDGES, 128>>>(comb, rel, dyn, edge_index, edge_type);

    dim3 cw1(IN_DIM / 32, HID_DIM / 32);
    convW1_kernel<<<cw1, dim3(32, 8)>>>(W1, p_W1T);

    // gemm1: h = tanh(embh @ W1T^T + b1), HMMA, K'=1536
    dim3 g1(E_EDGES / BM, HID_DIM / BN);   // (32, 8)
    gemm_mma<K1P * 2, K1P / BK, true><<<g1, 256, SMEM_NEED>>>(p_embh, p_W1T, b1, p_A2);

    // gemm2: pred = A2 @ B2^T + b2, K=1024
    dim3 g2(E_EDGES / BM, NPAD / BN);      // (32, 392)
    gemm_mma<KDIM * 2, KDIM / BK, false><<<g2, 256, SMEM_NEED>>>(p_A2, p_B2, b2, pred);

    lse_kernel<<<E_EDGES, 256>>>(pred, target_tails, node_id);
    final_kernel<<<1, 256>>>(out, off);
}

// round 15
// speedup vs baseline: 1.5045x; 1.5045x over previous
#include <cuda_runtime.h>
#include <cuda_fp16.h>
#include <math.h>
#include <stdint.h>

#define E_EDGES   4096
#define COMB_DIM  256
#define REL_DIM   128
#define IN_DIM    512
#define HID_DIM   1024
#define NE        50000
#define KDIM      1024           // GEMM2 K (plain fp16)
#define K1P       1536           // GEMM1 K' = 3 * 512 (hi/lo/hi split)
#define NPAD      50176          // 392 * 128
#define BM        128
#define BN        128
#define BK        64

// ---------------- device scratch (allocation-free rule) ----------------
__device__ float  g_row_lp[E_EDGES];
__device__ __half g_embh[(size_t)E_EDGES * K1P];     // 12 MB  (A of gemm1, triple)
__device__ __half g_W1T[(size_t)HID_DIM * K1P];      // 3 MB   (B of gemm1, triple)
__device__ __half g_A2[(size_t)E_EDGES * KDIM];      // 8 MB   (fp16 h)
__device__ __half g_B2[(size_t)NPAD * KDIM];         // 103 MB (fp16 W2^T)

// ---------------- PTX helpers ----------------
__device__ __forceinline__ uint32_t smem_u32(const void* p) {
    uint32_t a;
    asm("{ .reg .u64 t; cvta.to.shared.u64 t, %1; cvt.u32.u64 %0, t; }"
        : "=r"(a) : "l"(p));
    return a;
}
#define CP_ASYNC16(smem, gptr) \
    asm volatile("cp.async.cg.shared.global [%0], [%1], 16;" \
                 :: "r"(smem), "l"(gptr) : "memory")
#define CP_COMMIT() asm volatile("cp.async.commit_group;" ::: "memory")
#define CP_WAIT(n)  asm volatile("cp.async.wait_group %0;" :: "n"(n) : "memory")

#define LDMATRIX_X4(r0, r1, r2, r3, addr) \
    asm volatile("ldmatrix.sync.aligned.m8n8.x4.shared.b16 {%0,%1,%2,%3}, [%4];" \
                 : "=r"(r0), "=r"(r1), "=r"(r2), "=r"(r3) : "r"(addr))

#define MMA16816(d, a, b0, b1) \
    asm volatile("mma.sync.aligned.m16n8k16.row.col.f32.f16.f16.f32 " \
                 "{%0,%1,%2,%3}, {%4,%5,%6,%7}, {%8,%9}, {%0,%1,%2,%3};" \
                 : "+f"((d)[0]), "+f"((d)[1]), "+f"((d)[2]), "+f"((d)[3]) \
                 : "r"((a)[0]), "r"((a)[1]), "r"((a)[2]), "r"((a)[3]), \
                   "r"(b0), "r"(b1))

#define SWZ(off) ((off) ^ (((off) >> 3) & 0x70))

// ---------------------------------------------------------------------------
// 1) Gather -> fp16 triple [hi, lo, hi] per source value (row = 1536 halves)
// ---------------------------------------------------------------------------
__global__ void gather_kernel(const float* __restrict__ comb,
                              const float* __restrict__ rel,
                              const float* __restrict__ dyn,
                              const int* __restrict__ edge_index,
                              const int* __restrict__ edge_type) {
    int e = blockIdx.x;
    int head = edge_index[e];
    int rt   = edge_type[e];
    int col = threadIdx.x * 4;
    float4 v;
    if (col < COMB_DIM) {
        v = *(const float4*)(comb + (size_t)head * COMB_DIM + col);
    } else if (col < COMB_DIM + REL_DIM) {
        v = *(const float4*)(rel + (size_t)rt * REL_DIM + (col - COMB_DIM));
    } else {
        int d = col - (COMB_DIM + REL_DIM);
        const float* base = dyn + (size_t)rt * (4 * REL_DIM * 2) + 3 * (REL_DIM * 2);
        v.x = base[2 * (d + 0) + 1]; v.y = base[2 * (d + 1) + 1];
        v.z = base[2 * (d + 2) + 1]; v.w = base[2 * (d + 3) + 1];
    }
    __half2* dst = (__half2*)(g_embh + (size_t)e * K1P + 3 * (size_t)col);
    float x[4] = {v.x, v.y, v.z, v.w};
    __half h[12];
#pragma unroll
    for (int i = 0; i < 4; i++) {
        __half hi = __float2half(x[i]);
        __half lo = __float2half(x[i] - __half2float(hi));
        h[3 * i] = hi; h[3 * i + 1] = lo; h[3 * i + 2] = hi;
    }
#pragma unroll
    for (int i = 0; i < 6; i++)
        dst[i] = __halves2half2(h[2 * i], h[2 * i + 1]);
}

// ---------------------------------------------------------------------------
// 2) W1[k][n] -> W1T[n][3k] = [hi, hi, lo]   (512 x 1024 -> 1024 x 1536)
// ---------------------------------------------------------------------------
__global__ void convW1_kernel(const float* __restrict__ W1,
                              __half* __restrict__ W1T) {
    __shared__ float tile[32][33];
    int k0 = blockIdx.x * 32;
    int n0 = blockIdx.y * 32;
    int tx = threadIdx.x, ty = threadIdx.y;   // 32 x 8
#pragma unroll
    for (int i = 0; i < 4; i++) {
        int k = k0 + ty + 8 * i, n = n0 + tx;
        tile[ty + 8 * i][tx] = W1[(size_t)k * HID_DIM + n];
    }
    __syncthreads();
#pragma unroll
    for (int i = 0; i < 4; i++) {
        int n = n0 + ty + 8 * i, k = k0 + tx;
        float x = tile[tx][ty + 8 * i];
        __half hi = __float2half(x);
        __half lo = __float2half(x - __half2float(hi));
        size_t o = (size_t)n * K1P + 3 * (size_t)k;
        W1T[o] = hi; W1T[o + 1] = hi; W1T[o + 2] = lo;
    }
}

// ---------------------------------------------------------------------------
// 3) W2[k][n] -> B2[n][k] fp16 transpose; zero rows for n >= NE
// ---------------------------------------------------------------------------
__global__ void convB_kernel(const float* __restrict__ W2,
                             __half* __restrict__ B2) {
    __shared__ float tile[32][33];
    int k0 = blockIdx.x * 32;
    int n0 = blockIdx.y * 32;
    int tx = threadIdx.x, ty = threadIdx.y;   // 32 x 8
#pragma unroll
    for (int i = 0; i < 4; i++) {
        int k = k0 + ty + 8 * i, n = n0 + tx;
        tile[ty + 8 * i][tx] = (n < NE) ? W2[(size_t)k * NE + n] : 0.0f;
    }
    __syncthreads();
#pragma unroll
    for (int i = 0; i < 4; i++) {
        int n = n0 + ty + 8 * i, k = k0 + tx;
        B2[(size_t)n * KDIM + k] = __float2half(tile[tx][ty + 8 * i]);
    }
}

// ---------------------------------------------------------------------------
// 4) Templated HMMA GEMM: 128x128 tile, BK=64, 3-stage cp.async, 8 warps
//    TANH_OUT=true : out = fp16 tanh(acc+bias), ldc = KDIM, no N guard
//    TANH_OUT=false: out = fp32 acc+bias,       ldc = NE,   N guard
// ---------------------------------------------------------------------------
#define STAGE_BYTES 32768       // 16KB A + 16KB B
#define SMEM_NEED   (3 * STAGE_BYTES + 1024)

template<int LD_BYTES, int NT, bool TANH_OUT>
__global__ __launch_bounds__(256)
void gemm_mma(const __half* __restrict__ A, const __half* __restrict__ B,
              const float* __restrict__ bias, void* __restrict__ Cv) {
    extern __shared__ char smem_raw[];
    char* smem = (char*)(((uintptr_t)smem_raw + 1023) & ~(uintptr_t)1023);
    const uint32_t sbase = smem_u32(smem);
    const int tid = threadIdx.x;
    const int wid = tid >> 5, lane = tid & 31;
    const int warp_m = wid >> 1;       // 0..3
    const int warp_n = wid & 1;        // 0..1
    const int bm = blockIdx.x * BM;
    const int bn = blockIdx.y * BN;

    const char* gA = (const char*)A;
    const char* gB = (const char*)B;

    auto load_tile = [&](int s, int t) {
        const size_t kb = (size_t)t * (BK * 2);
        uint32_t aS = sbase + s * STAGE_BYTES;
        uint32_t bS = aS + 16384;
#pragma unroll
        for (int i = 0; i < 4; i++) {
            int idx = tid + i * 256;
            int row = idx >> 3, c16 = idx & 7;
            uint32_t off = (uint32_t)(row * 128 + c16 * 16);
            CP_ASYNC16(aS + SWZ(off), gA + (size_t)(bm + row) * LD_BYTES + kb + c16 * 16);
        }
#pragma unroll
        for (int i = 0; i < 4; i++) {
            int idx = tid + i * 256;
            int row = idx >> 3, c16 = idx & 7;
            uint32_t off = (uint32_t)(row * 128 + c16 * 16);
            CP_ASYNC16(bS + SWZ(off), gB + (size_t)(bn + row) * LD_BYTES + kb + c16 * 16);
        }
    };

    float acc[2][8][4];
#pragma unroll
    for (int mi = 0; mi < 2; mi++)
#pragma unroll
        for (int nj = 0; nj < 8; nj++)
#pragma unroll
            for (int r = 0; r < 4; r++) acc[mi][nj][r] = 0.0f;

    const int a_row_in16 = ((lane >> 3) & 1) * 8 + (lane & 7);
    const int a_khalf16  = (lane >> 4);
    const int b_row_in16 = ((lane >> 4) << 3) + (lane & 7);
    const int b_khalf16  = (lane >> 3) & 1;

    load_tile(0, 0); CP_COMMIT();
    load_tile(1, 1); CP_COMMIT();

    for (int t = 0; t < NT; t++) {
        if (t + 2 < NT) { load_tile((t + 2) % 3, t + 2); CP_COMMIT(); CP_WAIT(2); }
        else if (t + 1 < NT) { CP_WAIT(1); }
        else { CP_WAIT(0); }
        __syncthreads();

        uint32_t aS = sbase + (t % 3) * STAGE_BYTES;
        uint32_t bS = aS + 16384;
#pragma unroll
        for (int kk = 0; kk < 4; kk++) {
            uint32_t a[2][4];
#pragma unroll
            for (int mi = 0; mi < 2; mi++) {
                int row = warp_m * 32 + mi * 16 + a_row_in16;
                uint32_t off = (uint32_t)(kk * 32 + a_khalf16 * 16) ^ ((row & 7) << 4);
                LDMATRIX_X4(a[mi][0], a[mi][1], a[mi][2], a[mi][3],
                            aS + row * 128 + off);
            }
            uint32_t b[4][4];
#pragma unroll
            for (int nb = 0; nb < 4; nb++) {
                int row = warp_n * 64 + nb * 16 + b_row_in16;
                uint32_t off = (uint32_t)(kk * 32 + b_khalf16 * 16) ^ ((row & 7) << 4);
                LDMATRIX_X4(b[nb][0], b[nb][1], b[nb][2], b[nb][3],
                            bS + row * 128 + off);
            }
#pragma unroll
            for (int mi = 0; mi < 2; mi++)
#pragma unroll
                for (int nj = 0; nj < 8; nj++) {
                    int nb = nj >> 1, hi = (nj & 1) * 2;
                    MMA16816(acc[mi][nj], a[mi], b[nb][hi], b[nb][hi + 1]);
                }
        }
        __syncthreads();
    }

    const int r0 = lane >> 2;
    const int c0 = (lane & 3) * 2;
    if (TANH_OUT) {
        __half* Ch = (__half*)Cv;
#pragma unroll
        for (int nj = 0; nj < 8; nj++) {
            int col = bn + warp_n * 64 + nj * 8 + c0;
            float bv0 = bias[col], bv1 = bias[col + 1];
#pragma unroll
            for (int mi = 0; mi < 2; mi++) {
                int row = bm + warp_m * 32 + mi * 16 + r0;
                *(__half2*)(Ch + (size_t)row * KDIM + col) =
                    __floats2half2_rn(tanhf(acc[mi][nj][0] + bv0),
                                      tanhf(acc[mi][nj][1] + bv1));
                *(__half2*)(Ch + (size_t)(row + 8) * KDIM + col) =
                    __floats2half2_rn(tanhf(acc[mi][nj][2] + bv0),
                                      tanhf(acc[mi][nj][3] + bv1));
            }
        }
    } else {
        float* C = (float*)Cv;
#pragma unroll
        for (int nj = 0; nj < 8; nj++) {
            int col = bn + warp_n * 64 + nj * 8 + c0;
            if (col >= NE) continue;
            float bv0 = bias[col], bv1 = bias[col + 1];
#pragma unroll
            for (int mi = 0; mi < 2; mi++) {
                int row = bm + warp_m * 32 + mi * 16 + r0;
                float* p0 = C + (size_t)row * NE + col;
                p0[0] = acc[mi][nj][0] + bv0;
                p0[1] = acc[mi][nj][1] + bv1;
                float* p1 = C + (size_t)(row + 8) * NE + col;
                p1[0] = acc[mi][nj][2] + bv0;
                p1[1] = acc[mi][nj][3] + bv1;
            }
        }
    }
}

// ---------------------------------------------------------------------------
// 5) Single-pass online logsumexp + label log-prob
// ---------------------------------------------------------------------------
__global__ void lse_kernel(const float* __restrict__ pred,
                           const int* __restrict__ target_tails,
                           const int* __restrict__ node_id) {
    int row = blockIdx.x;
    const float* p = pred + (size_t)row * NE;
    __shared__ float sm[256], ss[256];
    int tid = threadIdx.x;

    float m = -3.402823e38f, s = 0.0f;
    for (int j = tid; j < NE; j += 256) {
        float v = p[j];
        if (v > m) { s = s * __expf(m - v) + 1.0f; m = v; }
        else       { s += __expf(v - m); }
    }
    sm[tid] = m; ss[tid] = s;
    __syncthreads();
    for (int st = 128; st > 0; st >>= 1) {
        if (tid < st) {
            float m1 = sm[tid], m2 = sm[tid + st];
            float M = fmaxf(m1, m2);
            ss[tid] = ss[tid] * __expf(m1 - M) + ss[tid + st] * __expf(m2 - M);
            sm[tid] = M;
        }
        __syncthreads();
    }
    if (tid == 0) {
        int label = node_id[target_tails[row]];
        g_row_lp[row] = p[label] - (sm[0] + logf(ss[0]));
    }
}

__global__ void final_kernel(float* __restrict__ out, int scalar_off) {
    __shared__ float red[256];
    int tid = threadIdx.x;
    float s = 0.0f;
    for (int j = tid; j < E_EDGES; j += 256) s += g_row_lp[j];
    red[tid] = s;
    __syncthreads();
    for (int t = 128; t > 0; t >>= 1) {
        if (tid < t) red[tid] += red[tid + t];
        __syncthreads();
    }
    if (tid == 0 && scalar_off >= 1) out[0] = red[0] / (float)E_EDGES;
}

// ---------------------------------------------------------------------------
extern "C" void kernel_launch(void* const* d_in, const int* in_sizes, int n_in,
                              void* d_out, int out_size) {
    const float* comb         = (const float*)d_in[0];
    const float* rel          = (const float*)d_in[1];
    const float* dyn          = (const float*)d_in[2];
    const float* W1           = (const float*)d_in[3];
    const float* b1           = (const float*)d_in[4];
    const float* W2           = (const float*)d_in[5];
    const float* b2           = (const float*)d_in[6];
    const int*   edge_index   = (const int*)d_in[7];
    const int*   edge_type    = (const int*)d_in[8];
    const int*   target_tails = (const int*)d_in[9];
    const int*   node_id      = (const int*)d_in[10];
    float* out = (float*)d_out;

    long long total = (long long)E_EDGES * (long long)NE;
    int off = (int)((long long)out_size - total);
    if (off < 0) off = 0;
    float* pred = out + off;

    void *p_embh_v, *p_W1T_v, *p_A2_v, *p_B2_v;
    cudaGetSymbolAddress(&p_embh_v, g_embh);
    cudaGetSymbolAddress(&p_W1T_v, g_W1T);
    cudaGetSymbolAddress(&p_A2_v, g_A2);
    cudaGetSymbolAddress(&p_B2_v, g_B2);
    __half* p_embh = (__half*)p_embh_v;
    __half* p_W1T  = (__half*)p_W1T_v;
    __half* p_A2   = (__half*)p_A2_v;
    __half* p_B2   = (__half*)p_B2_v;

    static bool attr_set = false;
    if (!attr_set) {
        cudaFuncSetAttribute((const void*)gemm_mma<K1P * 2, K1P / BK, true>,
                             cudaFuncAttributeMaxDynamicSharedMemorySize, SMEM_NEED);
        cudaFuncSetAttribute((const void*)gemm_mma<KDIM * 2, KDIM / BK, false>,
                             cudaFuncAttributeMaxDynamicSharedMemorySize, SMEM_NEED);
        attr_set = true;
    }

    // big independent conversion first
    dim3 cbG(KDIM / 32, NPAD / 32);
    convB_kernel<<<cbG, dim3(32, 8)>>>(W2, p_B2);

    gather_kernel<<<E_EDGES, 128>>>(comb, rel, dyn, edge_index, edge_type);

    dim3 cw1(IN_DIM / 32, HID_DIM / 32);
    convW1_kernel<<<cw1, dim3(32, 8)>>>(W1, p_W1T);

    // gemm1: h = tanh(embh @ W1T^T + b1), HMMA, K'=1536
    dim3 g1(E_EDGES / BM, HID_DIM / BN);   // (32, 8)
    gemm_mma<K1P * 2, K1P / BK, true><<<g1, 256, SMEM_NEED>>>(p_embh, p_W1T, b1, p_A2);

    // gemm2: pred = A2 @ B2^T + b2, K=1024
    dim3 g2(E_EDGES / BM, NPAD / BN);      // (32, 392)
    gemm_mma<KDIM * 2, KDIM / BK, false><<<g2, 256, SMEM_NEED>>>(p_A2, p_B2, b2, pred);

    lse_kernel<<<E_EDGES, 256>>>(pred, target_tails, node_id);
    final_kernel<<<1, 256>>>(out, off);
}

// round 16
// speedup vs baseline: 1.5094x; 1.0033x over previous
#include <cuda_runtime.h>
#include <cuda_fp16.h>
#include <math.h>
#include <stdint.h>

#define E_EDGES   4096
#define COMB_DIM  256
#define REL_DIM   128
#define IN_DIM    512
#define HID_DIM   1024
#define NE        50000
#define KDIM      1024           // GEMM2 K (plain fp16)
#define K1P       1536           // GEMM1 K' = 3 * 512 (hi/lo/hi split)
#define NPAD      50176          // 392 * 128
#define BM        128
#define BN        128
#define BK        64

// ---------------- device scratch (allocation-free rule) ----------------
__device__ float  g_row_lp[E_EDGES];
__device__ __half g_embh[(size_t)E_EDGES * K1P];     // 12 MB  (A of gemm1, triple)
__device__ __half g_W1T[(size_t)HID_DIM * K1P];      // 3 MB   (B of gemm1, triple)
__device__ __half g_A2[(size_t)E_EDGES * KDIM];      // 8 MB   (fp16 h)
__device__ __half g_B2[(size_t)NPAD * KDIM];         // 103 MB (fp16 W2^T)

// ---------------- PTX helpers ----------------
__device__ __forceinline__ uint32_t smem_u32(const void* p) {
    uint32_t a;
    asm("{ .reg .u64 t; cvta.to.shared.u64 t, %1; cvt.u32.u64 %0, t; }"
        : "=r"(a) : "l"(p));
    return a;
}
#define CP_ASYNC16(smem, gptr) \
    asm volatile("cp.async.cg.shared.global [%0], [%1], 16;" \
                 :: "r"(smem), "l"(gptr) : "memory")
#define CP_COMMIT() asm volatile("cp.async.commit_group;" ::: "memory")
#define CP_WAIT(n)  asm volatile("cp.async.wait_group %0;" :: "n"(n) : "memory")

#define LDMATRIX_X4(r0, r1, r2, r3, addr) \
    asm volatile("ldmatrix.sync.aligned.m8n8.x4.shared.b16 {%0,%1,%2,%3}, [%4];" \
                 : "=r"(r0), "=r"(r1), "=r"(r2), "=r"(r3) : "r"(addr))

#define MMA16816(d, a, b0, b1) \
    asm volatile("mma.sync.aligned.m16n8k16.row.col.f32.f16.f16.f32 " \
                 "{%0,%1,%2,%3}, {%4,%5,%6,%7}, {%8,%9}, {%0,%1,%2,%3};" \
                 : "+f"((d)[0]), "+f"((d)[1]), "+f"((d)[2]), "+f"((d)[3]) \
                 : "r"((a)[0]), "r"((a)[1]), "r"((a)[2]), "r"((a)[3]), \
                   "r"(b0), "r"(b1))

#define SWZ(off) ((off) ^ (((off) >> 3) & 0x70))

// ---------------------------------------------------------------------------
// 1) Gather -> fp16 triple [hi, lo, hi] per source value (row = 1536 halves)
// ---------------------------------------------------------------------------
__global__ void gather_kernel(const float* __restrict__ comb,
                              const float* __restrict__ rel,
                              const float* __restrict__ dyn,
                              const int* __restrict__ edge_index,
                              const int* __restrict__ edge_type) {
    int e = blockIdx.x;
    int head = edge_index[e];
    int rt   = edge_type[e];
    int col = threadIdx.x * 4;
    float4 v;
    if (col < COMB_DIM) {
        v = *(const float4*)(comb + (size_t)head * COMB_DIM + col);
    } else if (col < COMB_DIM + REL_DIM) {
        v = *(const float4*)(rel + (size_t)rt * REL_DIM + (col - COMB_DIM));
    } else {
        int d = col - (COMB_DIM + REL_DIM);
        const float* base = dyn + (size_t)rt * (4 * REL_DIM * 2) + 3 * (REL_DIM * 2);
        v.x = base[2 * (d + 0) + 1]; v.y = base[2 * (d + 1) + 1];
        v.z = base[2 * (d + 2) + 1]; v.w = base[2 * (d + 3) + 1];
    }
    __half2* dst = (__half2*)(g_embh + (size_t)e * K1P + 3 * (size_t)col);
    float x[4] = {v.x, v.y, v.z, v.w};
    __half h[12];
#pragma unroll
    for (int i = 0; i < 4; i++) {
        __half hi = __float2half(x[i]);
        __half lo = __float2half(x[i] - __half2float(hi));
        h[3 * i] = hi; h[3 * i + 1] = lo; h[3 * i + 2] = hi;
    }
#pragma unroll
    for (int i = 0; i < 6; i++)
        dst[i] = __halves2half2(h[2 * i], h[2 * i + 1]);
}

// ---------------------------------------------------------------------------
// 2) W1[k][n] -> W1T[n][3k] = [hi, hi, lo]   (512 x 1024 -> 1024 x 1536)
// ---------------------------------------------------------------------------
__global__ void convW1_kernel(const float* __restrict__ W1,
                              __half* __restrict__ W1T) {
    __shared__ float tile[32][33];
    int k0 = blockIdx.x * 32;
    int n0 = blockIdx.y * 32;
    int tx = threadIdx.x, ty = threadIdx.y;   // 32 x 8
#pragma unroll
    for (int i = 0; i < 4; i++) {
        int k = k0 + ty + 8 * i, n = n0 + tx;
        tile[ty + 8 * i][tx] = W1[(size_t)k * HID_DIM + n];
    }
    __syncthreads();
#pragma unroll
    for (int i = 0; i < 4; i++) {
        int n = n0 + ty + 8 * i, k = k0 + tx;
        float x = tile[tx][ty + 8 * i];
        __half hi = __float2half(x);
        __half lo = __float2half(x - __half2float(hi));
        size_t o = (size_t)n * K1P + 3 * (size_t)k;
        W1T[o] = hi; W1T[o + 1] = hi; W1T[o + 2] = lo;
    }
}

// ---------------------------------------------------------------------------
// 3) W2[k][n] -> B2[n][k] fp16 transpose; zero rows for n >= NE
// ---------------------------------------------------------------------------
__global__ void convB_kernel(const float* __restrict__ W2,
                             __half* __restrict__ B2) {
    __shared__ float tile[32][33];
    int k0 = blockIdx.x * 32;
    int n0 = blockIdx.y * 32;
    int tx = threadIdx.x, ty = threadIdx.y;   // 32 x 8
#pragma unroll
    for (int i = 0; i < 4; i++) {
        int k = k0 + ty + 8 * i, n = n0 + tx;
        tile[ty + 8 * i][tx] = (n < NE) ? W2[(size_t)k * NE + n] : 0.0f;
    }
    __syncthreads();
#pragma unroll
    for (int i = 0; i < 4; i++) {
        int n = n0 + ty + 8 * i, k = k0 + tx;
        B2[(size_t)n * KDIM + k] = __float2half(tile[tx][ty + 8 * i]);
    }
}

// ---------------------------------------------------------------------------
// 4) Templated HMMA GEMM: 128x128 tile, BK=64, 3-stage cp.async, 8 warps
//    TANH_OUT=true : out = fp16 tanh(acc+bias), ldc = KDIM, no N guard
//    TANH_OUT=false: out = fp32 acc+bias,       ldc = NE,   N guard
// ---------------------------------------------------------------------------
#define STAGE_BYTES 32768       // 16KB A + 16KB B
#define SMEM_NEED   (3 * STAGE_BYTES + 1024)

template<int LD_BYTES, int NT, bool TANH_OUT>
__global__ __launch_bounds__(256)
void gemm_mma(const __half* __restrict__ A, const __half* __restrict__ B,
              const float* __restrict__ bias, void* __restrict__ Cv) {
    extern __shared__ char smem_raw[];
    char* smem = (char*)(((uintptr_t)smem_raw + 1023) & ~(uintptr_t)1023);
    const uint32_t sbase = smem_u32(smem);
    const int tid = threadIdx.x;
    const int wid = tid >> 5, lane = tid & 31;
    const int warp_m = wid >> 1;       // 0..3
    const int warp_n = wid & 1;        // 0..1
    const int bm = blockIdx.x * BM;
    const int bn = blockIdx.y * BN;

    const char* gA = (const char*)A;
    const char* gB = (const char*)B;

    auto load_tile = [&](int s, int t) {
        const size_t kb = (size_t)t * (BK * 2);
        uint32_t aS = sbase + s * STAGE_BYTES;
        uint32_t bS = aS + 16384;
#pragma unroll
        for (int i = 0; i < 4; i++) {
            int idx = tid + i * 256;
            int row = idx >> 3, c16 = idx & 7;
            uint32_t off = (uint32_t)(row * 128 + c16 * 16);
            CP_ASYNC16(aS + SWZ(off), gA + (size_t)(bm + row) * LD_BYTES + kb + c16 * 16);
        }
#pragma unroll
        for (int i = 0; i < 4; i++) {
            int idx = tid + i * 256;
            int row = idx >> 3, c16 = idx & 7;
            uint32_t off = (uint32_t)(row * 128 + c16 * 16);
            CP_ASYNC16(bS + SWZ(off), gB + (size_t)(bn + row) * LD_BYTES + kb + c16 * 16);
        }
    };

    float acc[2][8][4];
#pragma unroll
    for (int mi = 0; mi < 2; mi++)
#pragma unroll
        for (int nj = 0; nj < 8; nj++)
#pragma unroll
            for (int r = 0; r < 4; r++) acc[mi][nj][r] = 0.0f;

    const int a_row_in16 = ((lane >> 3) & 1) * 8 + (lane & 7);
    const int a_khalf16  = (lane >> 4);
    const int b_row_in16 = ((lane >> 4) << 3) + (lane & 7);
    const int b_khalf16  = (lane >> 3) & 1;

    load_tile(0, 0); CP_COMMIT();
    load_tile(1, 1); CP_COMMIT();

    for (int t = 0; t < NT; t++) {
        if (t + 2 < NT) { load_tile((t + 2) % 3, t + 2); CP_COMMIT(); CP_WAIT(2); }
        else if (t + 1 < NT) { CP_WAIT(1); }
        else { CP_WAIT(0); }
        __syncthreads();

        uint32_t aS = sbase + (t % 3) * STAGE_BYTES;
        uint32_t bS = aS + 16384;
#pragma unroll
        for (int kk = 0; kk < 4; kk++) {
            uint32_t a[2][4];
#pragma unroll
            for (int mi = 0; mi < 2; mi++) {
                int row = warp_m * 32 + mi * 16 + a_row_in16;
                uint32_t off = (uint32_t)(kk * 32 + a_khalf16 * 16) ^ ((row & 7) << 4);
                LDMATRIX_X4(a[mi][0], a[mi][1], a[mi][2], a[mi][3],
                            aS + row * 128 + off);
            }
            uint32_t b[4][4];
#pragma unroll
            for (int nb = 0; nb < 4; nb++) {
                int row = warp_n * 64 + nb * 16 + b_row_in16;
                uint32_t off = (uint32_t)(kk * 32 + b_khalf16 * 16) ^ ((row & 7) << 4);
                LDMATRIX_X4(b[nb][0], b[nb][1], b[nb][2], b[nb][3],
                            bS + row * 128 + off);
            }
#pragma unroll
            for (int mi = 0; mi < 2; mi++)
#pragma unroll
                for (int nj = 0; nj < 8; nj++) {
                    int nb = nj >> 1, hi = (nj & 1) * 2;
                    MMA16816(acc[mi][nj], a[mi], b[nb][hi], b[nb][hi + 1]);
                }
        }
        __syncthreads();
    }

    const int r0 = lane >> 2;
    const int c0 = (lane & 3) * 2;
    if (TANH_OUT) {
        __half* Ch = (__half*)Cv;
#pragma unroll
        for (int nj = 0; nj < 8; nj++) {
            int col = bn + warp_n * 64 + nj * 8 + c0;
            float bv0 = bias[col], bv1 = bias[col + 1];
#pragma unroll
            for (int mi = 0; mi < 2; mi++) {
                int row = bm + warp_m * 32 + mi * 16 + r0;
                *(__half2*)(Ch + (size_t)row * KDIM + col) =
                    __floats2half2_rn(tanhf(acc[mi][nj][0] + bv0),
                                      tanhf(acc[mi][nj][1] + bv1));
                *(__half2*)(Ch + (size_t)(row + 8) * KDIM + col) =
                    __floats2half2_rn(tanhf(acc[mi][nj][2] + bv0),
                                      tanhf(acc[mi][nj][3] + bv1));
            }
        }
    } else {
        float* C = (float*)Cv;
#pragma unroll
        for (int nj = 0; nj < 8; nj++) {
            int col = bn + warp_n * 64 + nj * 8 + c0;
            if (col >= NE) continue;
            float bv0 = bias[col], bv1 = bias[col + 1];
#pragma unroll
            for (int mi = 0; mi < 2; mi++) {
                int row = bm + warp_m * 32 + mi * 16 + r0;
                float* p0 = C + (size_t)row * NE + col;
                p0[0] = acc[mi][nj][0] + bv0;
                p0[1] = acc[mi][nj][1] + bv1;
                float* p1 = C + (size_t)(row + 8) * NE + col;
                p1[0] = acc[mi][nj][2] + bv0;
                p1[1] = acc[mi][nj][3] + bv1;
            }
        }
    }
}

// ---------------------------------------------------------------------------
// 5) Single-pass online logsumexp + label log-prob
// ---------------------------------------------------------------------------
__global__ void lse_kernel(const float* __restrict__ pred,
                           const int* __restrict__ target_tails,
                           const int* __restrict__ node_id) {
    int row = blockIdx.x;
    const float* p = pred + (size_t)row * NE;
    __shared__ float sm[256], ss[256];
    int tid = threadIdx.x;

    float m = -3.402823e38f, s = 0.0f;
    for (int j = tid; j < NE; j += 256) {
        float v = p[j];
        if (v > m) { s = s * __expf(m - v) + 1.0f; m = v; }
        else       { s += __expf(v - m); }
    }
    sm[tid] = m; ss[tid] = s;
    __syncthreads();
    for (int st = 128; st > 0; st >>= 1) {
        if (tid < st) {
            float m1 = sm[tid], m2 = sm[tid + st];
            float M = fmaxf(m1, m2);
            ss[tid] = ss[tid] * __expf(m1 - M) + ss[tid + st] * __expf(m2 - M);
            sm[tid] = M;
        }
        __syncthreads();
    }
    if (tid == 0) {
        int label = node_id[target_tails[row]];
        g_row_lp[row] = p[label] - (sm[0] + logf(ss[0]));
    }
}

__global__ void final_kernel(float* __restrict__ out, int scalar_off) {
    __shared__ float red[256];
    int tid = threadIdx.x;
    float s = 0.0f;
    for (int j = tid; j < E_EDGES; j += 256) s += g_row_lp[j];
    red[tid] = s;
    __syncthreads();
    for (int t = 128; t > 0; t >>= 1) {
        if (tid < t) red[tid] += red[tid + t];
        __syncthreads();
    }
    if (tid == 0 && scalar_off >= 1) out[0] = red[0] / (float)E_EDGES;
}

// ---------------------------------------------------------------------------
extern "C" void kernel_launch(void* const* d_in, const int* in_sizes, int n_in,
                              void* d_out, int out_size) {
    const float* comb         = (const float*)d_in[0];
    const float* rel          = (const float*)d_in[1];
    const float* dyn          = (const float*)d_in[2];
    const float* W1           = (const float*)d_in[3];
    const float* b1           = (const float*)d_in[4];
    const float* W2           = (const float*)d_in[5];
    const float* b2           = (const float*)d_in[6];
    const int*   edge_index   = (const int*)d_in[7];
    const int*   edge_type    = (const int*)d_in[8];
    const int*   target_tails = (const int*)d_in[9];
    const int*   node_id      = (const int*)d_in[10];
    float* out = (float*)d_out;

    long long total = (long long)E_EDGES * (long long)NE;
    int off = (int)((long long)out_size - total);
    if (off < 0) off = 0;
    float* pred = out + off;

    void *p_embh_v, *p_W1T_v, *p_A2_v, *p_B2_v;
    cudaGetSymbolAddress(&p_embh_v, g_embh);
    cudaGetSymbolAddress(&p_W1T_v, g_W1T);
    cudaGetSymbolAddress(&p_A2_v, g_A2);
    cudaGetSymbolAddress(&p_B2_v, g_B2);
    __half* p_embh = (__half*)p_embh_v;
    __half* p_W1T  = (__half*)p_W1T_v;
    __half* p_A2   = (__half*)p_A2_v;
    __half* p_B2   = (__half*)p_B2_v;

    static bool attr_set = false;
    if (!attr_set) {
        cudaFuncSetAttribute((const void*)gemm_mma<K1P * 2, K1P / BK, true>,
                             cudaFuncAttributeMaxDynamicSharedMemorySize, SMEM_NEED);
        cudaFuncSetAttribute((const void*)gemm_mma<KDIM * 2, KDIM / BK, false>,
                             cudaFuncAttributeMaxDynamicSharedMemorySize, SMEM_NEED);
        attr_set = true;
    }

    // big independent conversion first
    dim3 cbG(KDIM / 32, NPAD / 32);
    convB_kernel<<<cbG, dim3(32, 8)>>>(W2, p_B2);

    gather_kernel<<<E_EDGES, 128>>>(comb, rel, dyn, edge_index, edge_type);

    dim3 cw1(IN_DIM / 32, HID_DIM / 32);
    convW1_kernel<<<cw1, dim3(32, 8)>>>(W1, p_W1T);

    // gemm1: h = tanh(embh @ W1T^T + b1), HMMA, K'=1536
    dim3 g1(E_EDGES / BM, HID_DIM / BN);   // (32, 8)
    gemm_mma<K1P * 2, K1P / BK, true><<<g1, 256, SMEM_NEED>>>(p_embh, p_W1T, b1, p_A2);

    // gemm2: pred = A2 @ B2^T + b2, K=1024
    dim3 g2(E_EDGES / BM, NPAD / BN);      // (32, 392)
    gemm_mma<KDIM * 2, KDIM / BK, false><<<g2, 256, SMEM_NEED>>>(p_A2, p_B2, b2, pred);

    lse_kernel<<<E_EDGES, 256>>>(pred, target_tails, node_id);
    final_kernel<<<1, 256>>>(out, off);
}